// round 3
// baseline (speedup 1.0000x reference)
#include <cuda_runtime.h>
#include <math_constants.h>

#define BN 2
#define NP 65536
#define MR 128
#define NS 6
#define KK 2048
#define NBS (BN*NS)

#define FT 128          // FPS threads
#define NSLOT 40        // register slots/thread -> capacity 5120 candidates
#define CAP (FT*NSLOT)

// ---- scratch (__device__ globals: allocation-free) ----
__device__ float4        g_comp[NBS][NP];   // compacted candidates (x,y,z, orig idx bits)
__device__ float         g_dmin[NBS][NP];   // FPS fallback dmin (cnt > CAP only)
__device__ unsigned char g_sec [BN][NP];    // sector code 0..6, 255 = invalid
__device__ int g_cnt[BN][NS];
__device__ int g_total[BN];                 // reset at end of k_out each launch
__device__ int g_nk [BN][NS];
__device__ int g_off[BN][NS];
__device__ int g_stotal[BN];
__device__ int g_buf[BN][KK];

// ---- classify: branchless d2 argmin + single deferred sqrt; exact cleanup on near-tie ----
__global__ void __launch_bounds__(256) k_classify(const float* __restrict__ points,
                                                  const float* __restrict__ rois) {
    __shared__ float4 sroi[MR];  // cx, cy, cz(adjusted), thr = maxdim + 1.6
    int b = blockIdx.y;
    int tid = threadIdx.x;
    if (tid < MR) {
        const float* r = rois + (b * MR + tid) * 7;
        float cx = r[0], cy = r[1], cz = r[2];
        float dx = r[3], dy = r[4], dz = r[5];
        cz = __fadd_rn(cz, __fmul_rn(dz, 0.5f));
        float hx = __fmul_rn(dx, 0.5f), hy = __fmul_rn(dy, 0.5f), hz = __fmul_rn(dz, 0.5f);
        float md = __fsqrt_rn(__fadd_rn(__fadd_rn(__fmul_rn(hx, hx), __fmul_rn(hy, hy)),
                                        __fmul_rn(hz, hz)));
        sroi[tid] = make_float4(cx, cy, cz, __fadd_rn(md, 1.6f));
    }
    __syncthreads();

    int i = blockIdx.x * blockDim.x + tid;
    const float* p = points + ((size_t)b * NP + i) * 3;
    float px = p[0], py = p[1], pz = p[2];

    float m1 = CUDART_INF_F, m2 = CUDART_INF_F;
    int bi = 0;
    #pragma unroll 4
    for (int m = 0; m < MR; m++) {
        float4 c = sroi[m];
        float ax = __fsub_rn(px, c.x);
        float ay = __fsub_rn(py, c.y);
        float az = __fsub_rn(pz, c.z);
        float d2 = __fadd_rn(__fadd_rn(__fmul_rn(ax, ax), __fmul_rn(ay, ay)),
                             __fmul_rn(az, az));
        float mx = fmaxf(d2, m1);
        m2 = fminf(m2, mx);             // runner-up value
        if (d2 < m1) { m1 = d2; bi = m; }  // strict <: first-index tie-break
    }
    float s1 = __fsqrt_rn(m1);
    // d2-argmin == sqrt-argmin unless two d2 round to the same sqrt; detect & redo exactly.
    if (__fsqrt_rn(m2) == s1) {
        float bsv = CUDART_INF_F; int bi2 = 0;
        for (int m = 0; m < MR; m++) {
            float4 c = sroi[m];
            float ax = __fsub_rn(px, c.x);
            float ay = __fsub_rn(py, c.y);
            float az = __fsub_rn(pz, c.z);
            float d2 = __fadd_rn(__fadd_rn(__fmul_rn(ax, ax), __fmul_rn(ay, ay)),
                                 __fmul_rn(az, az));
            float sd = __fsqrt_rn(d2);
            if (sd < bsv) { bsv = sd; bi2 = m; }
        }
        s1 = bsv; bi = bi2;
    }
    bool valid = s1 < sroi[bi].w;

    float ang = __fadd_rn(atan2f(py, px), 3.14159265358979323846f);
    float fs  = floorf(__fdiv_rn(ang, 1.04719755119659774615f));
    fs = fminf(fmaxf(fs, 0.0f), 6.0f);
    int s = (int)fs;

    g_sec[b][i] = valid ? (unsigned char)s : (unsigned char)255;

    unsigned mask = __ballot_sync(0xffffffffu, valid);
    if ((tid & 31) == 0 && mask) atomicAdd(&g_total[b], __popc(mask));
}

// ---- stable stream compaction per (b,s) ----
__global__ void __launch_bounds__(1024) k_compact(const float* __restrict__ points) {
    int bs = blockIdx.x;
    int b = bs / NS, s = bs - b * NS;
    __shared__ int wsum[32];
    __shared__ int sBase;
    int tid = threadIdx.x;
    int lane = tid & 31, wid = tid >> 5;
    if (tid == 0) sBase = 0;
    __syncthreads();
    const unsigned char* sec = g_sec[b];
    const float* pts = points + (size_t)b * NP * 3;
    for (int base = 0; base < NP; base += 1024) {
        int i = base + tid;
        bool f = (sec[i] == (unsigned char)s);
        unsigned m = __ballot_sync(0xffffffffu, f);
        int wpos = __popc(m & ((1u << lane) - 1u));
        if (lane == 0) wsum[wid] = __popc(m);
        __syncthreads();
        if (wid == 0) {
            int v = wsum[lane];
            #pragma unroll
            for (int o = 1; o < 32; o <<= 1) {
                int u = __shfl_up_sync(0xffffffffu, v, o);
                if (lane >= o) v += u;
            }
            wsum[lane] = v;
        }
        __syncthreads();
        if (f) {
            int pos = sBase + (wid ? wsum[wid - 1] : 0) + wpos;
            float4 q;
            q.x = pts[3 * i];
            q.y = pts[3 * i + 1];
            q.z = pts[3 * i + 2];
            q.w = __int_as_float(i);
            g_comp[bs][pos] = q;
        }
        __syncthreads();
        if (tid == 0) sBase += wsum[31];
        __syncthreads();
    }
    if (tid == 0) g_cnt[b][s] = sBase;
}

// ---- per-sector budgets ----
__global__ void k_budget() {
    int b = threadIdx.x;
    if (b >= BN) return;
    int total = g_total[b];
    if (total < 1) total = 1;
    int sum = 0;
    for (int s = 0; s < NS; s++) {
        int c = g_cnt[b][s];
        float q = __fdiv_rn(__fmul_rn((float)c, 2048.0f), (float)total);
        int nk = (int)ceilf(q);
        if (nk > c) nk = c;
        g_off[b][s] = sum;
        g_nk[b][s]  = nk;
        sum += nk;
    }
    g_stotal[b] = (sum < 1) ? 1 : sum;
}

// ---- FPS v3: register-resident candidates + dmin; one barrier per pick ----
__global__ void __launch_bounds__(FT) k_fps3() {
    int bs = blockIdx.x;
    int b = bs / NS;
    int cnt = g_cnt[b][bs - b * NS];
    int nk  = g_nk[b][bs - b * NS];
    int off = g_off[b][bs - b * NS];
    if (nk <= 0 || off >= KK) return;
    int nEff = nk;
    if (off + nEff > KK) nEff = KK - off;

    __shared__ unsigned sV[2][4];
    __shared__ unsigned sI[2][4];

    int tid = threadIdx.x, lane = tid & 31, wid = tid >> 5;
    const float4* __restrict__ comp = g_comp[bs];

    float4 p0 = comp[0];
    if (tid == 0) g_buf[b][off] = __float_as_int(p0.w);
    float lx = p0.x, ly = p0.y, lz = p0.z;

    if (cnt <= CAP) {
        // ---- register-resident path ----
        float cx[NSLOT], cy[NSLOT], cz[NSLOT], dm[NSLOT];
        #pragma unroll
        for (int k = 0; k < NSLOT; k++) {
            int i = k * FT + tid;
            if (i < cnt) {
                float4 p = comp[i];
                cx[k] = p.x; cy[k] = p.y; cz[k] = p.z;
                dm[k] = CUDART_INF_F;           // fmin with d2 gives d2 (d2 << 1e10)
            } else {
                cx[k] = 0.0f; cy[k] = 0.0f; cz[k] = 0.0f;
                dm[k] = -CUDART_INF_F;          // never wins argmax
            }
        }

        for (int j = 1; j < nEff; j++) {
            float vmax = -CUDART_INF_F;
            unsigned vidx = 0x7fffffffu;
            #pragma unroll
            for (int k = 0; k < NSLOT; k++) {
                if (k * FT < cnt) {             // block-uniform: dead slots skipped
                    float ax = __fsub_rn(cx[k], lx);
                    float ay = __fsub_rn(cy[k], ly);
                    float az = __fsub_rn(cz[k], lz);
                    float d2 = __fadd_rn(__fadd_rn(__fmul_rn(ax, ax), __fmul_rn(ay, ay)),
                                         __fmul_rn(az, az));
                    float dmn = fminf(dm[k], d2);   // -inf slots stay -inf
                    dm[k] = dmn;
                    if (dmn > vmax) { vmax = dmn; vidx = (unsigned)(k * FT + tid); }
                }
            }
            // warp argmax: max on float bits (valid dmin >= 0), then min index
            unsigned vb = (vmax < 0.0f) ? 0u : __float_as_uint(vmax);
            unsigned wm = __reduce_max_sync(0xffffffffu, vb);
            unsigned ci = (vb == wm) ? vidx : 0xffffffffu;
            unsigned wi = __reduce_min_sync(0xffffffffu, ci);
            int par = j & 1;
            if (lane == 0) { sV[par][wid] = wm; sI[par][wid] = wi; }
            __syncthreads();
            // every thread combines the 4 warp results (no 2nd stage, no 2nd bar)
            unsigned bv = sV[par][0], bp = sI[par][0];
            #pragma unroll
            for (int w2 = 1; w2 < 4; w2++) {
                unsigned v = sV[par][w2], i2 = sI[par][w2];
                if (v > bv || (v == bv && i2 < bp)) { bv = v; bp = i2; }
            }
            float4 pw = __ldg(&comp[bp]);       // L1-resident broadcast
            lx = pw.x; ly = pw.y; lz = pw.z;
            if (tid == 0) g_buf[b][off + j] = __float_as_int(pw.w);
        }
    } else {
        // ---- gmem fallback (rare; correctness net) ----
        float* __restrict__ D = g_dmin[bs];
        for (int j = 1; j < nEff; j++) {
            float vmax = -CUDART_INF_F;
            unsigned vidx = 0x7fffffffu;
            for (int i = tid; i < cnt; i += FT) {
                float4 p = comp[i];
                float ax = __fsub_rn(p.x, lx), ay = __fsub_rn(p.y, ly), az = __fsub_rn(p.z, lz);
                float d2 = __fadd_rn(__fadd_rn(__fmul_rn(ax, ax), __fmul_rn(ay, ay)),
                                     __fmul_rn(az, az));
                float dmn = (j == 1) ? d2 : fminf(D[i], d2);
                D[i] = dmn;
                if (dmn > vmax) { vmax = dmn; vidx = (unsigned)i; }
            }
            unsigned vb = (vmax < 0.0f) ? 0u : __float_as_uint(vmax);
            unsigned wm = __reduce_max_sync(0xffffffffu, vb);
            unsigned ci = (vb == wm) ? vidx : 0xffffffffu;
            unsigned wi = __reduce_min_sync(0xffffffffu, ci);
            int par = j & 1;
            if (lane == 0) { sV[par][wid] = wm; sI[par][wid] = wi; }
            __syncthreads();
            unsigned bv = sV[par][0], bp = sI[par][0];
            #pragma unroll
            for (int w2 = 1; w2 < 4; w2++) {
                unsigned v = sV[par][w2], i2 = sI[par][w2];
                if (v > bv || (v == bv && i2 < bp)) { bv = v; bp = i2; }
            }
            float4 pw = comp[bp];
            lx = pw.x; ly = pw.y; lz = pw.z;
            if (tid == 0) g_buf[b][off + j] = __float_as_int(pw.w);
        }
    }
}

// ---- gather output + reset g_total for the next launch ----
__global__ void k_out(const float* __restrict__ points, float* __restrict__ out) {
    int t = blockIdx.x * blockDim.x + threadIdx.x;
    if (t >= BN * KK) return;
    int b = t / KK, i = t - b * KK;
    int st = g_stotal[b];
    int src = g_buf[b][i % st];
    const float* p = points + ((size_t)b * NP + src) * 3;
    out[3 * t + 0] = p[0];
    out[3 * t + 1] = p[1];
    out[3 * t + 2] = p[2];
    if (t < BN) g_total[t] = 0;   // ready for next graph replay
}

extern "C" void kernel_launch(void* const* d_in, const int* in_sizes, int n_in,
                              void* d_out, int out_size) {
    const float* points = (const float*)d_in[0];  // [2,65536,3] f32
    const float* rois   = (const float*)d_in[1];  // [2,128,7]  f32
    float* out = (float*)d_out;                   // [2,2048,3] f32

    dim3 gc(NP / 256, BN);
    k_classify<<<gc, 256>>>(points, rois);
    k_compact<<<NBS, 1024>>>(points);
    k_budget<<<1, 32>>>();
    k_fps3<<<NBS, FT>>>();
    k_out<<<(BN * KK + 255) / 256, 256>>>(points, out);
}

// round 4
// speedup vs baseline: 1.6930x; 1.6930x over previous
#include <cuda_runtime.h>
#include <math_constants.h>

#define BN 2
#define NP 65536
#define MR 128
#define NS 6
#define KK 2048
#define NBS (BN*NS)

#define FT 256          // FPS threads (8 warps -> 2 per SMSP)
#define NSLOT 24        // register slots/thread -> capacity 6144 candidates
#define CHUNK 4         // slots per uniform guard branch
#define CAP (FT*NSLOT)

// ---- scratch (__device__ globals: allocation-free) ----
__device__ float4        g_comp[NBS][NP];   // compacted candidates (x,y,z, orig idx bits)
__device__ float         g_dmin[NBS][NP];   // FPS fallback dmin (cnt > CAP only)
__device__ unsigned char g_sec [BN][NP];    // sector code 0..6, 255 = invalid
__device__ int g_cnt[BN][NS];
__device__ int g_total[BN];                 // reset at end of k_out each launch
__device__ int g_nk [BN][NS];
__device__ int g_off[BN][NS];
__device__ int g_stotal[BN];
__device__ int g_buf[BN][KK];

// ---- classify: branchless d2 argmin + single deferred sqrt; exact cleanup on near-tie ----
__global__ void __launch_bounds__(256) k_classify(const float* __restrict__ points,
                                                  const float* __restrict__ rois) {
    __shared__ float4 sroi[MR];  // cx, cy, cz(adjusted), thr = maxdim + 1.6
    int b = blockIdx.y;
    int tid = threadIdx.x;
    if (tid < MR) {
        const float* r = rois + (b * MR + tid) * 7;
        float cx = r[0], cy = r[1], cz = r[2];
        float dx = r[3], dy = r[4], dz = r[5];
        cz = __fadd_rn(cz, __fmul_rn(dz, 0.5f));
        float hx = __fmul_rn(dx, 0.5f), hy = __fmul_rn(dy, 0.5f), hz = __fmul_rn(dz, 0.5f);
        float md = __fsqrt_rn(__fadd_rn(__fadd_rn(__fmul_rn(hx, hx), __fmul_rn(hy, hy)),
                                        __fmul_rn(hz, hz)));
        sroi[tid] = make_float4(cx, cy, cz, __fadd_rn(md, 1.6f));
    }
    __syncthreads();

    int i = blockIdx.x * blockDim.x + tid;
    const float* p = points + ((size_t)b * NP + i) * 3;
    float px = p[0], py = p[1], pz = p[2];

    float m1 = CUDART_INF_F, m2 = CUDART_INF_F;
    int bi = 0;
    #pragma unroll 4
    for (int m = 0; m < MR; m++) {
        float4 c = sroi[m];
        float ax = __fsub_rn(px, c.x);
        float ay = __fsub_rn(py, c.y);
        float az = __fsub_rn(pz, c.z);
        float d2 = __fadd_rn(__fadd_rn(__fmul_rn(ax, ax), __fmul_rn(ay, ay)),
                             __fmul_rn(az, az));
        float mx = fmaxf(d2, m1);
        m2 = fminf(m2, mx);             // runner-up value
        if (d2 < m1) { m1 = d2; bi = m; }  // strict <: first-index tie-break
    }
    float s1 = __fsqrt_rn(m1);
    // d2-argmin == sqrt-argmin unless two d2 round to the same sqrt; detect & redo exactly.
    if (__fsqrt_rn(m2) == s1) {
        float bsv = CUDART_INF_F; int bi2 = 0;
        for (int m = 0; m < MR; m++) {
            float4 c = sroi[m];
            float ax = __fsub_rn(px, c.x);
            float ay = __fsub_rn(py, c.y);
            float az = __fsub_rn(pz, c.z);
            float d2 = __fadd_rn(__fadd_rn(__fmul_rn(ax, ax), __fmul_rn(ay, ay)),
                                 __fmul_rn(az, az));
            float sd = __fsqrt_rn(d2);
            if (sd < bsv) { bsv = sd; bi2 = m; }
        }
        s1 = bsv; bi = bi2;
    }
    bool valid = s1 < sroi[bi].w;

    float ang = __fadd_rn(atan2f(py, px), 3.14159265358979323846f);
    float fs  = floorf(__fdiv_rn(ang, 1.04719755119659774615f));
    fs = fminf(fmaxf(fs, 0.0f), 6.0f);
    int s = (int)fs;

    g_sec[b][i] = valid ? (unsigned char)s : (unsigned char)255;

    unsigned mask = __ballot_sync(0xffffffffu, valid);
    if ((tid & 31) == 0 && mask) atomicAdd(&g_total[b], __popc(mask));
}

// ---- stable stream compaction per (b,s) ----
__global__ void __launch_bounds__(1024) k_compact(const float* __restrict__ points) {
    int bs = blockIdx.x;
    int b = bs / NS, s = bs - b * NS;
    __shared__ int wsum[32];
    __shared__ int sBase;
    int tid = threadIdx.x;
    int lane = tid & 31, wid = tid >> 5;
    if (tid == 0) sBase = 0;
    __syncthreads();
    const unsigned char* sec = g_sec[b];
    const float* pts = points + (size_t)b * NP * 3;
    for (int base = 0; base < NP; base += 1024) {
        int i = base + tid;
        bool f = (sec[i] == (unsigned char)s);
        unsigned m = __ballot_sync(0xffffffffu, f);
        int wpos = __popc(m & ((1u << lane) - 1u));
        if (lane == 0) wsum[wid] = __popc(m);
        __syncthreads();
        if (wid == 0) {
            int v = wsum[lane];
            #pragma unroll
            for (int o = 1; o < 32; o <<= 1) {
                int u = __shfl_up_sync(0xffffffffu, v, o);
                if (lane >= o) v += u;
            }
            wsum[lane] = v;
        }
        __syncthreads();
        if (f) {
            int pos = sBase + (wid ? wsum[wid - 1] : 0) + wpos;
            float4 q;
            q.x = pts[3 * i];
            q.y = pts[3 * i + 1];
            q.z = pts[3 * i + 2];
            q.w = __int_as_float(i);
            g_comp[bs][pos] = q;
        }
        __syncthreads();
        if (tid == 0) sBase += wsum[31];
        __syncthreads();
    }
    if (tid == 0) g_cnt[b][s] = sBase;
}

// ---- per-sector budgets ----
__global__ void k_budget() {
    int b = threadIdx.x;
    if (b >= BN) return;
    int total = g_total[b];
    if (total < 1) total = 1;
    int sum = 0;
    for (int s = 0; s < NS; s++) {
        int c = g_cnt[b][s];
        float q = __fdiv_rn(__fmul_rn((float)c, 2048.0f), (float)total);
        int nk = (int)ceilf(q);
        if (nk > c) nk = c;
        g_off[b][s] = sum;
        g_nk[b][s]  = nk;
        sum += nk;
    }
    g_stotal[b] = (sum < 1) ? 1 : sum;
}

// ---- FPS v4: register-resident, chunked guards (6 uniform branches/iter), 8 warps ----
__global__ void __launch_bounds__(FT) k_fps4() {
    int bs = blockIdx.x;
    int b = bs / NS;
    int cnt = g_cnt[b][bs - b * NS];
    int nk  = g_nk[b][bs - b * NS];
    int off = g_off[b][bs - b * NS];
    if (nk <= 0 || off >= KK) return;
    int nEff = nk;
    if (off + nEff > KK) nEff = KK - off;

    __shared__ unsigned sV[2][FT / 32];
    __shared__ unsigned sI[2][FT / 32];

    int tid = threadIdx.x, lane = tid & 31, wid = tid >> 5;
    const float4* __restrict__ comp = g_comp[bs];

    float4 p0 = comp[0];
    if (tid == 0) g_buf[b][off] = __float_as_int(p0.w);
    float lx = p0.x, ly = p0.y, lz = p0.z;

    if (cnt <= CAP) {
        // ---- register-resident path ----
        float cx[NSLOT], cy[NSLOT], cz[NSLOT], dm[NSLOT];
        #pragma unroll
        for (int k = 0; k < NSLOT; k++) {
            int i = k * FT + tid;
            if (i < cnt) {
                float4 p = comp[i];
                cx[k] = p.x; cy[k] = p.y; cz[k] = p.z;
                dm[k] = CUDART_INF_F;           // fmin(inf, d2) = d2 (matches 1e10 init)
            } else {
                cx[k] = 0.0f; cy[k] = 0.0f; cz[k] = 0.0f;
                dm[k] = -CUDART_INF_F;          // stays -inf forever; never wins argmax
            }
        }

        for (int j = 1; j < nEff; j++) {
            float vmax = -CUDART_INF_F;
            unsigned vidx = 0x7fffffffu;
            #pragma unroll
            for (int c = 0; c < NSLOT / CHUNK; c++) {
                if (c * CHUNK * FT < cnt) {     // block-uniform guard, 1 per CHUNK slots
                    #pragma unroll
                    for (int q = 0; q < CHUNK; q++) {
                        const int k = c * CHUNK + q;
                        float ax = __fsub_rn(cx[k], lx);
                        float ay = __fsub_rn(cy[k], ly);
                        float az = __fsub_rn(cz[k], lz);
                        float d2 = __fadd_rn(__fadd_rn(__fmul_rn(ax, ax), __fmul_rn(ay, ay)),
                                             __fmul_rn(az, az));
                        float dmn = fminf(dm[k], d2);   // -inf slots stay -inf
                        dm[k] = dmn;
                        if (dmn > vmax) { vmax = dmn; vidx = (unsigned)(k * FT + tid); }
                    }
                }
            }
            // warp argmax: max on float bits (valid dmin >= +0), then min index
            unsigned vb = (vmax < 0.0f) ? 0u : __float_as_uint(vmax);
            unsigned wm = __reduce_max_sync(0xffffffffu, vb);
            unsigned ci = (vb == wm) ? vidx : 0xffffffffu;
            unsigned wi = __reduce_min_sync(0xffffffffu, ci);
            int par = j & 1;
            if (lane == 0) { sV[par][wid] = wm; sI[par][wid] = wi; }
            __syncthreads();
            // every thread combines the 8 warp results (no 2nd stage, no 2nd barrier)
            unsigned bv = sV[par][0], bp = sI[par][0];
            #pragma unroll
            for (int w2 = 1; w2 < FT / 32; w2++) {
                unsigned v = sV[par][w2], i2 = sI[par][w2];
                if (v > bv || (v == bv && i2 < bp)) { bv = v; bp = i2; }
            }
            float4 pw = __ldg(&comp[bp]);       // L1-resident broadcast
            lx = pw.x; ly = pw.y; lz = pw.z;
            if (tid == 0) g_buf[b][off + j] = __float_as_int(pw.w);
        }
    } else {
        // ---- gmem fallback (rare; correctness net) ----
        float* __restrict__ D = g_dmin[bs];
        for (int j = 1; j < nEff; j++) {
            float vmax = -CUDART_INF_F;
            unsigned vidx = 0x7fffffffu;
            for (int i = tid; i < cnt; i += FT) {
                float4 p = comp[i];
                float ax = __fsub_rn(p.x, lx), ay = __fsub_rn(p.y, ly), az = __fsub_rn(p.z, lz);
                float d2 = __fadd_rn(__fadd_rn(__fmul_rn(ax, ax), __fmul_rn(ay, ay)),
                                     __fmul_rn(az, az));
                float dmn = (j == 1) ? d2 : fminf(D[i], d2);
                D[i] = dmn;
                if (dmn > vmax) { vmax = dmn; vidx = (unsigned)i; }
            }
            unsigned vb = (vmax < 0.0f) ? 0u : __float_as_uint(vmax);
            unsigned wm = __reduce_max_sync(0xffffffffu, vb);
            unsigned ci = (vb == wm) ? vidx : 0xffffffffu;
            unsigned wi = __reduce_min_sync(0xffffffffu, ci);
            int par = j & 1;
            if (lane == 0) { sV[par][wid] = wm; sI[par][wid] = wi; }
            __syncthreads();
            unsigned bv = sV[par][0], bp = sI[par][0];
            #pragma unroll
            for (int w2 = 1; w2 < FT / 32; w2++) {
                unsigned v = sV[par][w2], i2 = sI[par][w2];
                if (v > bv || (v == bv && i2 < bp)) { bv = v; bp = i2; }
            }
            float4 pw = comp[bp];
            lx = pw.x; ly = pw.y; lz = pw.z;
            if (tid == 0) g_buf[b][off + j] = __float_as_int(pw.w);
        }
    }
}

// ---- gather output + reset g_total for the next launch ----
__global__ void k_out(const float* __restrict__ points, float* __restrict__ out) {
    int t = blockIdx.x * blockDim.x + threadIdx.x;
    if (t >= BN * KK) return;
    int b = t / KK, i = t - b * KK;
    int st = g_stotal[b];
    int src = g_buf[b][i % st];
    const float* p = points + ((size_t)b * NP + src) * 3;
    out[3 * t + 0] = p[0];
    out[3 * t + 1] = p[1];
    out[3 * t + 2] = p[2];
    if (t < BN) g_total[t] = 0;   // ready for next graph replay
}

extern "C" void kernel_launch(void* const* d_in, const int* in_sizes, int n_in,
                              void* d_out, int out_size) {
    const float* points = (const float*)d_in[0];  // [2,65536,3] f32
    const float* rois   = (const float*)d_in[1];  // [2,128,7]  f32
    float* out = (float*)d_out;                   // [2,2048,3] f32

    dim3 gc(NP / 256, BN);
    k_classify<<<gc, 256>>>(points, rois);
    k_compact<<<NBS, 1024>>>(points);
    k_budget<<<1, 32>>>();
    k_fps4<<<NBS, FT>>>();
    k_out<<<(BN * KK + 255) / 256, 256>>>(points, out);
}

// round 5
// speedup vs baseline: 1.7108x; 1.0105x over previous
#include <cuda_runtime.h>
#include <math_constants.h>

#define BN 2
#define NP 65536
#define MR 128
#define NS 6
#define KK 2048
#define NBS (BN*NS)

#define FT 384          // FPS threads (12 warps -> 3 per SMSP)
#define NSLOT 16        // register slots/thread -> capacity 6144
#define NPAIR (NSLOT/2)
#define GUARD 4         // slots per uniform guard (2 pairs)
#define CAP (FT*NSLOT)

typedef unsigned long long u64;
__device__ __forceinline__ u64 f2pack(float lo, float hi) {
    u64 r; asm("mov.b64 %0,{%1,%2};" : "=l"(r) : "f"(lo), "f"(hi)); return r;
}
__device__ __forceinline__ void f2unpack(u64 v, float& lo, float& hi) {
    asm("mov.b64 {%0,%1},%2;" : "=f"(lo), "=f"(hi) : "l"(v));
}
__device__ __forceinline__ u64 add2(u64 a, u64 b) {
    u64 r; asm("add.rn.f32x2 %0,%1,%2;" : "=l"(r) : "l"(a), "l"(b)); return r;
}
__device__ __forceinline__ u64 mul2(u64 a, u64 b) {
    u64 r; asm("mul.rn.f32x2 %0,%1,%2;" : "=l"(r) : "l"(a), "l"(b)); return r;
}

// ---- scratch (__device__ globals: allocation-free) ----
__device__ float4        g_comp[NBS][NP];   // compacted candidates (x,y,z, orig idx bits)
__device__ float         g_dmin[NBS][NP];   // FPS fallback dmin (cnt > CAP only)
__device__ unsigned char g_sec [BN][NP];    // sector code 0..6, 255 = invalid
__device__ int g_cnt[BN][7];                // per-sector counts; [6] = valid-but-sector-6
__device__ int g_buf[BN][KK];

// ---- classify: branchless d2 argmin + single deferred sqrt; exact cleanup on near-tie ----
__global__ void __launch_bounds__(256) k_classify(const float* __restrict__ points,
                                                  const float* __restrict__ rois) {
    __shared__ float4 sroi[MR];  // cx, cy, cz(adjusted), thr = maxdim + 1.6
    int b = blockIdx.y;
    int tid = threadIdx.x;
    if (tid < MR) {
        const float* r = rois + (b * MR + tid) * 7;
        float cx = r[0], cy = r[1], cz = r[2];
        float dx = r[3], dy = r[4], dz = r[5];
        cz = __fadd_rn(cz, __fmul_rn(dz, 0.5f));
        float hx = __fmul_rn(dx, 0.5f), hy = __fmul_rn(dy, 0.5f), hz = __fmul_rn(dz, 0.5f);
        float md = __fsqrt_rn(__fadd_rn(__fadd_rn(__fmul_rn(hx, hx), __fmul_rn(hy, hy)),
                                        __fmul_rn(hz, hz)));
        sroi[tid] = make_float4(cx, cy, cz, __fadd_rn(md, 1.6f));
    }
    __syncthreads();

    int i = blockIdx.x * blockDim.x + tid;
    const float* p = points + ((size_t)b * NP + i) * 3;
    float px = p[0], py = p[1], pz = p[2];

    float m1 = CUDART_INF_F, m2 = CUDART_INF_F;
    int bi = 0;
    #pragma unroll 4
    for (int m = 0; m < MR; m++) {
        float4 c = sroi[m];
        float ax = __fsub_rn(px, c.x);
        float ay = __fsub_rn(py, c.y);
        float az = __fsub_rn(pz, c.z);
        float d2 = __fadd_rn(__fadd_rn(__fmul_rn(ax, ax), __fmul_rn(ay, ay)),
                             __fmul_rn(az, az));
        float mx = fmaxf(d2, m1);
        m2 = fminf(m2, mx);             // runner-up value
        if (d2 < m1) { m1 = d2; bi = m; }  // strict <: first-index tie-break
    }
    float s1 = __fsqrt_rn(m1);
    // d2-argmin == sqrt-argmin unless two d2 round to the same sqrt; detect & redo exactly.
    if (__fsqrt_rn(m2) == s1) {
        float bsv = CUDART_INF_F; int bi2 = 0;
        for (int m = 0; m < MR; m++) {
            float4 c = sroi[m];
            float ax = __fsub_rn(px, c.x);
            float ay = __fsub_rn(py, c.y);
            float az = __fsub_rn(pz, c.z);
            float d2 = __fadd_rn(__fadd_rn(__fmul_rn(ax, ax), __fmul_rn(ay, ay)),
                                 __fmul_rn(az, az));
            float sd = __fsqrt_rn(d2);
            if (sd < bsv) { bsv = sd; bi2 = m; }
        }
        s1 = bsv; bi = bi2;
    }
    bool valid = s1 < sroi[bi].w;

    float ang = __fadd_rn(atan2f(py, px), 3.14159265358979323846f);
    float fs  = floorf(__fdiv_rn(ang, 1.04719755119659774615f));
    fs = fminf(fmaxf(fs, 0.0f), 6.0f);
    int s = (int)fs;

    g_sec[b][i] = valid ? (unsigned char)s : (unsigned char)255;
}

// ---- compact v2: 1 warp per contiguous 2048-pt range, 2 barriers total ----
// blocks 0..11: compact sector s of batch b. blocks 12..13: count-only for sector 6.
__global__ void __launch_bounds__(1024) k_compact(const float* __restrict__ points) {
    int bs = blockIdx.x;
    int tid = threadIdx.x, lane = tid & 31, wid = tid >> 5;
    __shared__ int wcnt[32];
    __shared__ int woff[32];

    if (bs >= NBS) {  // count-only: sector 6 of batch b
        int b = bs - NBS;
        const unsigned char* sec = g_sec[b];
        int c = 0;
        for (int i = tid; i < NP; i += 1024)
            c += (sec[i] == (unsigned char)6);
        c = __reduce_add_sync(0xffffffffu, c);
        if (lane == 0) wcnt[wid] = c;
        __syncthreads();
        if (tid == 0) {
            int t = 0;
            for (int w = 0; w < 32; w++) t += wcnt[w];
            g_cnt[b][6] = t;
        }
        return;
    }

    int b = bs / NS, s = bs - b * NS;
    const unsigned char* sec = g_sec[b];
    const float* pts = points + (size_t)b * NP * 3;
    const int R = NP / 32;           // 2048 points per warp, contiguous (stable order)
    int r0 = wid * R;

    // pass 1: count per warp
    int c = 0;
    for (int t = 0; t < R / 32; t++) {
        int i = r0 + t * 32 + lane;
        unsigned m = __ballot_sync(0xffffffffu, sec[i] == (unsigned char)s);
        c += __popc(m);
    }
    if (lane == 0) wcnt[wid] = c;
    __syncthreads();
    // exclusive prefix over 32 warp counts
    if (wid == 0) {
        int v = wcnt[lane];
        int orig = v;
        #pragma unroll
        for (int o = 1; o < 32; o <<= 1) {
            int u = __shfl_up_sync(0xffffffffu, v, o);
            if (lane >= o) v += u;
        }
        woff[lane] = v - orig;
        if (lane == 31) g_cnt[b][s] = v;
    }
    __syncthreads();
    // pass 2: scatter
    int pos = woff[wid];
    float4* __restrict__ comp = g_comp[bs];
    for (int t = 0; t < R / 32; t++) {
        int i = r0 + t * 32 + lane;
        bool f = (sec[i] == (unsigned char)s);
        unsigned m = __ballot_sync(0xffffffffu, f);
        if (f) {
            float4 q;
            q.x = pts[3 * i];
            q.y = pts[3 * i + 1];
            q.z = pts[3 * i + 2];
            q.w = __int_as_float(i);
            comp[pos + __popc(m & ((1u << lane) - 1u))] = q;
        }
        pos += __popc(m);
    }
}

// budget for (b, s): returns nk and off (prefix of earlier sectors' nk)
__device__ __forceinline__ void budget(int b, int s, int& nk, int& off) {
    int cs[NS];
    int total = g_cnt[b][6];
    #pragma unroll
    for (int t = 0; t < NS; t++) { cs[t] = g_cnt[b][t]; total += cs[t]; }
    if (total < 1) total = 1;
    off = 0; nk = 0;
    #pragma unroll
    for (int t = 0; t < NS; t++) {
        float q = __fdiv_rn(__fmul_rn((float)cs[t], 2048.0f), (float)total);
        int n = (int)ceilf(q);
        if (n > cs[t]) n = cs[t];
        if (t < s) off += n;
        if (t == s) nk = n;
    }
}

// ---- FPS v5: register-resident, packed f32x2 distance, deferred argmax index ----
__global__ void __launch_bounds__(FT) k_fps5() {
    int bs = blockIdx.x;
    int b = bs / NS, s = bs - b * NS;
    int cnt = g_cnt[b][s];
    int nk, off;
    budget(b, s, nk, off);
    if (nk <= 0 || off >= KK) return;
    int nEff = nk;
    if (off + nEff > KK) nEff = KK - off;

    __shared__ unsigned sV[2][FT / 32];
    __shared__ unsigned sI[2][FT / 32];

    int tid = threadIdx.x, lane = tid & 31, wid = tid >> 5;
    const float4* __restrict__ comp = g_comp[bs];

    float4 p0 = comp[0];
    if (tid == 0) g_buf[b][off] = __float_as_int(p0.w);
    float lx = p0.x, ly = p0.y, lz = p0.z;

    if (cnt <= CAP) {
        // ---- register-resident path; candidates packed 2-per-64-bit ----
        u64 pxp[NPAIR], pyp[NPAIR], pzp[NPAIR];
        float dm[NSLOT];
        #pragma unroll
        for (int p = 0; p < NPAIR; p++) {
            int i0 = (2 * p) * FT + tid, i1 = (2 * p + 1) * FT + tid;
            float x0 = 0, y0 = 0, z0 = 0, x1 = 0, y1 = 0, z1 = 0;
            if (i0 < cnt) { float4 q = comp[i0]; x0 = q.x; y0 = q.y; z0 = q.z;
                            dm[2 * p] = CUDART_INF_F; }
            else dm[2 * p] = -CUDART_INF_F;                    // never wins argmax
            if (i1 < cnt) { float4 q = comp[i1]; x1 = q.x; y1 = q.y; z1 = q.z;
                            dm[2 * p + 1] = CUDART_INF_F; }
            else dm[2 * p + 1] = -CUDART_INF_F;
            pxp[p] = f2pack(x0, x1); pyp[p] = f2pack(y0, y1); pzp[p] = f2pack(z0, z1);
        }

        for (int j = 1; j < nEff; j++) {
            // x - y == x + (-y) exactly (IEEE): broadcast negated pivot
            u64 nlx2 = f2pack(-lx, -lx), nly2 = f2pack(-ly, -ly), nlz2 = f2pack(-lz, -lz);
            float vmax = -CUDART_INF_F;
            #pragma unroll
            for (int g = 0; g < NSLOT / GUARD; g++) {
                if (g * GUARD * FT < cnt) {      // block-uniform guard, 1 per GUARD slots
                    #pragma unroll
                    for (int q = 0; q < GUARD / 2; q++) {
                        const int p = g * (GUARD / 2) + q;
                        u64 ax = add2(pxp[p], nlx2);
                        u64 ay = add2(pyp[p], nly2);
                        u64 az = add2(pzp[p], nlz2);
                        u64 d2p = add2(add2(mul2(ax, ax), mul2(ay, ay)), mul2(az, az));
                        float d2a, d2b; f2unpack(d2p, d2a, d2b);
                        float a = fminf(dm[2 * p], d2a);      // -inf slots stay -inf
                        float c2 = fminf(dm[2 * p + 1], d2b);
                        dm[2 * p] = a; dm[2 * p + 1] = c2;
                        vmax = fmaxf(vmax, a);
                        vmax = fmaxf(vmax, c2);
                    }
                }
            }
            // recover lowest slot achieving vmax (descending predicated scan)
            unsigned vidx = 0x7fffffffu;
            #pragma unroll
            for (int k = NSLOT - 1; k >= 0; k--)
                if (dm[k] == vmax) vidx = (unsigned)(k * FT + tid);
            if (vmax < 0.0f) vidx = 0x7fffffffu;     // fully-dead thread
            unsigned vb = (vmax < 0.0f) ? 0u : __float_as_uint(vmax);
            unsigned wm = __reduce_max_sync(0xffffffffu, vb);
            unsigned ci = (vb == wm) ? vidx : 0xffffffffu;
            unsigned wi = __reduce_min_sync(0xffffffffu, ci);
            int par = j & 1;
            if (lane == 0) { sV[par][wid] = wm; sI[par][wid] = wi; }
            __syncthreads();
            unsigned bv = sV[par][0], bp = sI[par][0];
            #pragma unroll
            for (int w2 = 1; w2 < FT / 32; w2++) {
                unsigned v = sV[par][w2], i2 = sI[par][w2];
                if (v > bv || (v == bv && i2 < bp)) { bv = v; bp = i2; }
            }
            float4 pw = __ldg(&comp[bp]);       // L1-resident broadcast
            lx = pw.x; ly = pw.y; lz = pw.z;
            if (tid == 0) g_buf[b][off + j] = __float_as_int(pw.w);
        }
    } else {
        // ---- gmem fallback (rare; correctness net) ----
        float* __restrict__ D = g_dmin[bs];
        for (int j = 1; j < nEff; j++) {
            float vmax = -CUDART_INF_F;
            unsigned vidx = 0x7fffffffu;
            for (int i = tid; i < cnt; i += FT) {
                float4 p = comp[i];
                float ax = __fsub_rn(p.x, lx), ay = __fsub_rn(p.y, ly), az = __fsub_rn(p.z, lz);
                float d2 = __fadd_rn(__fadd_rn(__fmul_rn(ax, ax), __fmul_rn(ay, ay)),
                                     __fmul_rn(az, az));
                float dmn = (j == 1) ? d2 : fminf(D[i], d2);
                D[i] = dmn;
                if (dmn > vmax) { vmax = dmn; vidx = (unsigned)i; }
            }
            unsigned vb = (vmax < 0.0f) ? 0u : __float_as_uint(vmax);
            unsigned wm = __reduce_max_sync(0xffffffffu, vb);
            unsigned ci = (vb == wm) ? vidx : 0xffffffffu;
            unsigned wi = __reduce_min_sync(0xffffffffu, ci);
            int par = j & 1;
            if (lane == 0) { sV[par][wid] = wm; sI[par][wid] = wi; }
            __syncthreads();
            unsigned bv = sV[par][0], bp = sI[par][0];
            #pragma unroll
            for (int w2 = 1; w2 < FT / 32; w2++) {
                unsigned v = sV[par][w2], i2 = sI[par][w2];
                if (v > bv || (v == bv && i2 < bp)) { bv = v; bp = i2; }
            }
            float4 pw = comp[bp];
            lx = pw.x; ly = pw.y; lz = pw.z;
            if (tid == 0) g_buf[b][off + j] = __float_as_int(pw.w);
        }
    }
}

// ---- gather output ----
__global__ void k_out(const float* __restrict__ points, float* __restrict__ out) {
    int t = blockIdx.x * blockDim.x + threadIdx.x;
    if (t >= BN * KK) return;
    int b = t / KK, i = t - b * KK;
    // stotal = sum of (unclipped-position) per-sector budgets
    int cs[NS];
    int total = g_cnt[b][6];
    #pragma unroll
    for (int s = 0; s < NS; s++) { cs[s] = g_cnt[b][s]; total += cs[s]; }
    if (total < 1) total = 1;
    int st = 0;
    #pragma unroll
    for (int s = 0; s < NS; s++) {
        float q = __fdiv_rn(__fmul_rn((float)cs[s], 2048.0f), (float)total);
        int n = (int)ceilf(q);
        if (n > cs[s]) n = cs[s];
        st += n;
    }
    if (st < 1) st = 1;
    int src = g_buf[b][i % st];
    const float* p = points + ((size_t)b * NP + src) * 3;
    out[3 * t + 0] = p[0];
    out[3 * t + 1] = p[1];
    out[3 * t + 2] = p[2];
}

extern "C" void kernel_launch(void* const* d_in, const int* in_sizes, int n_in,
                              void* d_out, int out_size) {
    const float* points = (const float*)d_in[0];  // [2,65536,3] f32
    const float* rois   = (const float*)d_in[1];  // [2,128,7]  f32
    float* out = (float*)d_out;                   // [2,2048,3] f32

    dim3 gc(NP / 256, BN);
    k_classify<<<gc, 256>>>(points, rois);
    k_compact<<<NBS + BN, 1024>>>(points);
    k_fps5<<<NBS, FT>>>();
    k_out<<<(BN * KK + 255) / 256, 256>>>(points, out);
}

// round 6
// speedup vs baseline: 2.7958x; 1.6342x over previous
#include <cuda_runtime.h>
#include <math_constants.h>

#define BN 2
#define NP 65536
#define MR 128
#define NS 6
#define KK 2048
#define NBS (BN*NS)

#define FT 384          // FPS threads (12 warps -> 3 per SMSP)
#define NW (FT/32)      // 12 warps
#define MAXP 8          // max candidate pairs per thread
#define CAP (FT*2*MAXP) // 6144 candidates
#define SMEM_FPS (4*CAP*4)   // sx, sy, sz, sw

typedef unsigned long long u64;
__device__ __forceinline__ u64 f2pack(float lo, float hi) {
    u64 r; asm("mov.b64 %0,{%1,%2};" : "=l"(r) : "f"(lo), "f"(hi)); return r;
}
__device__ __forceinline__ void f2unpack(u64 v, float& lo, float& hi) {
    asm("mov.b64 {%0,%1},%2;" : "=f"(lo), "=f"(hi) : "l"(v));
}
__device__ __forceinline__ u64 add2(u64 a, u64 b) {
    u64 r; asm("add.rn.f32x2 %0,%1,%2;" : "=l"(r) : "l"(a), "l"(b)); return r;
}
__device__ __forceinline__ u64 mul2(u64 a, u64 b) {
    u64 r; asm("mul.rn.f32x2 %0,%1,%2;" : "=l"(r) : "l"(a), "l"(b)); return r;
}

// ---- scratch (__device__ globals: allocation-free) ----
__device__ float4        g_comp[NBS][NP];   // compacted candidates (x,y,z, orig idx bits)
__device__ float         g_dmin[NBS][NP];   // FPS fallback dmin (cnt > CAP only)
__device__ unsigned char g_sec [BN][NP];    // sector code 0..6, 255 = invalid
__device__ int g_cnt[BN][7];                // per-sector counts; [6] = valid-but-sector-6
__device__ int g_buf[BN][KK];

// ---- classify: branchless d2 argmin + single deferred sqrt; exact cleanup on near-tie ----
__global__ void __launch_bounds__(256) k_classify(const float* __restrict__ points,
                                                  const float* __restrict__ rois) {
    __shared__ float4 sroi[MR];  // cx, cy, cz(adjusted), thr = maxdim + 1.6
    int b = blockIdx.y;
    int tid = threadIdx.x;
    if (tid < MR) {
        const float* r = rois + (b * MR + tid) * 7;
        float cx = r[0], cy = r[1], cz = r[2];
        float dx = r[3], dy = r[4], dz = r[5];
        cz = __fadd_rn(cz, __fmul_rn(dz, 0.5f));
        float hx = __fmul_rn(dx, 0.5f), hy = __fmul_rn(dy, 0.5f), hz = __fmul_rn(dz, 0.5f);
        float md = __fsqrt_rn(__fadd_rn(__fadd_rn(__fmul_rn(hx, hx), __fmul_rn(hy, hy)),
                                        __fmul_rn(hz, hz)));
        sroi[tid] = make_float4(cx, cy, cz, __fadd_rn(md, 1.6f));
    }
    __syncthreads();

    int i = blockIdx.x * blockDim.x + tid;
    const float* p = points + ((size_t)b * NP + i) * 3;
    float px = p[0], py = p[1], pz = p[2];

    float m1 = CUDART_INF_F, m2 = CUDART_INF_F;
    int bi = 0;
    #pragma unroll 4
    for (int m = 0; m < MR; m++) {
        float4 c = sroi[m];
        float ax = __fsub_rn(px, c.x);
        float ay = __fsub_rn(py, c.y);
        float az = __fsub_rn(pz, c.z);
        float d2 = __fadd_rn(__fadd_rn(__fmul_rn(ax, ax), __fmul_rn(ay, ay)),
                             __fmul_rn(az, az));
        float mx = fmaxf(d2, m1);
        m2 = fminf(m2, mx);             // runner-up value
        if (d2 < m1) { m1 = d2; bi = m; }  // strict <: first-index tie-break
    }
    float s1 = __fsqrt_rn(m1);
    // d2-argmin == sqrt-argmin unless two d2 round to the same sqrt; detect & redo exactly.
    if (__fsqrt_rn(m2) == s1) {
        float bsv = CUDART_INF_F; int bi2 = 0;
        for (int m = 0; m < MR; m++) {
            float4 c = sroi[m];
            float ax = __fsub_rn(px, c.x);
            float ay = __fsub_rn(py, c.y);
            float az = __fsub_rn(pz, c.z);
            float d2 = __fadd_rn(__fadd_rn(__fmul_rn(ax, ax), __fmul_rn(ay, ay)),
                                 __fmul_rn(az, az));
            float sd = __fsqrt_rn(d2);
            if (sd < bsv) { bsv = sd; bi2 = m; }
        }
        s1 = bsv; bi = bi2;
    }
    bool valid = s1 < sroi[bi].w;

    float ang = __fadd_rn(atan2f(py, px), 3.14159265358979323846f);
    float fs  = floorf(__fdiv_rn(ang, 1.04719755119659774615f));
    fs = fminf(fmaxf(fs, 0.0f), 6.0f);
    int s = (int)fs;

    g_sec[b][i] = valid ? (unsigned char)s : (unsigned char)255;
}

// ---- compact: 1 warp per contiguous 2048-pt range, 2 barriers total ----
__global__ void __launch_bounds__(1024) k_compact(const float* __restrict__ points) {
    int bs = blockIdx.x;
    int tid = threadIdx.x, lane = tid & 31, wid = tid >> 5;
    __shared__ int wcnt[32];
    __shared__ int woff[32];

    if (bs >= NBS) {  // count-only: sector 6 of batch b
        int b = bs - NBS;
        const unsigned char* sec = g_sec[b];
        int c = 0;
        for (int i = tid; i < NP; i += 1024)
            c += (sec[i] == (unsigned char)6);
        c = __reduce_add_sync(0xffffffffu, c);
        if (lane == 0) wcnt[wid] = c;
        __syncthreads();
        if (tid == 0) {
            int t = 0;
            for (int w = 0; w < 32; w++) t += wcnt[w];
            g_cnt[b][6] = t;
        }
        return;
    }

    int b = bs / NS, s = bs - b * NS;
    const unsigned char* sec = g_sec[b];
    const float* pts = points + (size_t)b * NP * 3;
    const int R = NP / 32;           // 2048 points per warp, contiguous (stable order)
    int r0 = wid * R;

    int c = 0;
    for (int t = 0; t < R / 32; t++) {
        int i = r0 + t * 32 + lane;
        unsigned m = __ballot_sync(0xffffffffu, sec[i] == (unsigned char)s);
        c += __popc(m);
    }
    if (lane == 0) wcnt[wid] = c;
    __syncthreads();
    if (wid == 0) {
        int v = wcnt[lane];
        int orig = v;
        #pragma unroll
        for (int o = 1; o < 32; o <<= 1) {
            int u = __shfl_up_sync(0xffffffffu, v, o);
            if (lane >= o) v += u;
        }
        woff[lane] = v - orig;
        if (lane == 31) g_cnt[b][s] = v;
    }
    __syncthreads();
    int pos = woff[wid];
    float4* __restrict__ comp = g_comp[bs];
    for (int t = 0; t < R / 32; t++) {
        int i = r0 + t * 32 + lane;
        bool f = (sec[i] == (unsigned char)s);
        unsigned m = __ballot_sync(0xffffffffu, f);
        if (f) {
            float4 q;
            q.x = pts[3 * i];
            q.y = pts[3 * i + 1];
            q.z = pts[3 * i + 2];
            q.w = __int_as_float(i);
            comp[pos + __popc(m & ((1u << lane) - 1u))] = q;
        }
        pos += __popc(m);
    }
}

// budget for (b, s): returns nk and off (prefix of earlier sectors' nk)
__device__ __forceinline__ void budget(int b, int s, int& nk, int& off) {
    int cs[NS];
    int total = g_cnt[b][6];
    #pragma unroll
    for (int t = 0; t < NS; t++) { cs[t] = g_cnt[b][t]; total += cs[t]; }
    if (total < 1) total = 1;
    off = 0; nk = 0;
    #pragma unroll
    for (int t = 0; t < NS; t++) {
        float q = __fdiv_rn(__fmul_rn((float)cs[t], 2048.0f), (float)total);
        int n = (int)ceilf(q);
        if (n > cs[t]) n = cs[t];
        if (t < s) off += n;
        if (t == s) nk = n;
    }
}

// ---- FPS v6 inner loop: value-only hot loop, lazy index recovery ----
template<int P>
__device__ __forceinline__ void fps_loop(
    int b, int off, int nEff, int cnt, const float4* __restrict__ comp,
    const float* __restrict__ sx, const float* __restrict__ sy,
    const float* __restrict__ sz, const float* __restrict__ sw,
    float (*sV)[NW], int* sIdx)
{
    int tid = threadIdx.x, lane = tid & 31, wid = tid >> 5;
    u64 pxp[P], pyp[P], pzp[P];
    float dm[2 * P];
    #pragma unroll
    for (int p = 0; p < P; p++) {
        int i0 = (2 * p) * FT + tid, i1 = (2 * p + 1) * FT + tid;
        float x0 = 0, y0 = 0, z0 = 0, x1 = 0, y1 = 0, z1 = 0;
        if (i0 < cnt) { float4 q = comp[i0]; x0 = q.x; y0 = q.y; z0 = q.z;
                        dm[2 * p] = CUDART_INF_F; }
        else dm[2 * p] = -CUDART_INF_F;
        if (i1 < cnt) { float4 q = comp[i1]; x1 = q.x; y1 = q.y; z1 = q.z;
                        dm[2 * p + 1] = CUDART_INF_F; }
        else dm[2 * p + 1] = -CUDART_INF_F;
        pxp[p] = f2pack(x0, x1); pyp[p] = f2pack(y0, y1); pzp[p] = f2pack(z0, z1);
    }
    float lx = sx[0], ly = sy[0], lz = sz[0];

    for (int j = 1; j < nEff; j++) {
        int par = j & 1;
        u64 nlx = f2pack(-lx, -lx), nly = f2pack(-ly, -ly), nlz = f2pack(-lz, -lz);
        float vmax = -CUDART_INF_F;
        #pragma unroll
        for (int p = 0; p < P; p++) {
            u64 ax = add2(pxp[p], nlx);
            u64 ay = add2(pyp[p], nly);
            u64 az = add2(pzp[p], nlz);
            u64 d2p = add2(add2(mul2(ax, ax), mul2(ay, ay)), mul2(az, az));
            float d2a, d2b; f2unpack(d2p, d2a, d2b);
            float a = fminf(dm[2 * p], d2a);          // -inf slots stay -inf
            float c = fminf(dm[2 * p + 1], d2b);
            dm[2 * p] = a; dm[2 * p + 1] = c;
            vmax = fmaxf(vmax, fmaxf(a, c));
        }
        unsigned vb = (vmax < 0.0f) ? 0u : __float_as_uint(vmax);
        unsigned wm = __reduce_max_sync(0xffffffffu, vb);    // bits order-iso for >= 0
        if (lane == 0) sV[par][wid] = __uint_as_float(wm);
        __syncthreads();
        if (tid == 0) sIdx[par ^ 1] = 0x7fffffff;   // reset other parity (safe window)
        // blockmax: 3 vector LDS + 11 FMNMX, value only
        float4 v0 = *(const float4*)&sV[par][0];
        float4 v1 = *(const float4*)&sV[par][4];
        float4 v2 = *(const float4*)&sV[par][8];
        float bm = fmaxf(fmaxf(fmaxf(v0.x, v0.y), fmaxf(v0.z, v0.w)),
                  fmaxf(fmaxf(fmaxf(v1.x, v1.y), fmaxf(v1.z, v1.w)),
                        fmaxf(fmaxf(v2.x, v2.y), fmaxf(v2.z, v2.w))));
        if (vmax == bm) {                            // ~1 thread; dead threads (-inf) never
            int cand = 0x7fffffff;
            #pragma unroll
            for (int k = 2 * P - 1; k >= 0; k--)     // ends at lowest matching slot
                if (dm[k] == bm) cand = k * FT + tid;
            atomicMin(&sIdx[par], cand);             // lowest global index = exact tie-break
        }
        __syncthreads();
        int widx = sIdx[par];
        lx = sx[widx]; ly = sy[widx]; lz = sz[widx];
        if (tid == 0) g_buf[b][off + j] = __float_as_int(sw[widx]);
    }
}

__global__ void __launch_bounds__(FT) k_fps6() {
    extern __shared__ float smf[];
    float* sx = smf;
    float* sy = sx + CAP;
    float* sz = sy + CAP;
    float* sw = sz + CAP;
    __shared__ __align__(16) float sV[2][NW];
    __shared__ int sIdx[2];
    __shared__ unsigned fV[2][NW], fI[2][NW];   // fallback reduction scratch

    int bs = blockIdx.x;
    int b = bs / NS, s = bs - b * NS;
    int cnt = g_cnt[b][s];
    int nk, off;
    budget(b, s, nk, off);
    if (nk <= 0 || off >= KK) return;
    int nEff = nk;
    if (off + nEff > KK) nEff = KK - off;

    int tid = threadIdx.x, lane = tid & 31, wid = tid >> 5;
    const float4* __restrict__ comp = g_comp[bs];

    if (cnt <= CAP) {
        for (int i = tid; i < cnt; i += FT) {
            float4 q = comp[i];
            sx[i] = q.x; sy[i] = q.y; sz[i] = q.z; sw[i] = q.w;
        }
        if (tid == 0) { sIdx[0] = 0x7fffffff; sIdx[1] = 0x7fffffff; }
        __syncthreads();
        if (tid == 0) g_buf[b][off] = __float_as_int(sw[0]);
        int pairs = (cnt + 2 * FT - 1) / (2 * FT);
        switch (pairs) {
            case 1: fps_loop<1>(b, off, nEff, cnt, comp, sx, sy, sz, sw, sV, sIdx); break;
            case 2: fps_loop<2>(b, off, nEff, cnt, comp, sx, sy, sz, sw, sV, sIdx); break;
            case 3: fps_loop<3>(b, off, nEff, cnt, comp, sx, sy, sz, sw, sV, sIdx); break;
            case 4: fps_loop<4>(b, off, nEff, cnt, comp, sx, sy, sz, sw, sV, sIdx); break;
            case 5: fps_loop<5>(b, off, nEff, cnt, comp, sx, sy, sz, sw, sV, sIdx); break;
            case 6: fps_loop<6>(b, off, nEff, cnt, comp, sx, sy, sz, sw, sV, sIdx); break;
            case 7: fps_loop<7>(b, off, nEff, cnt, comp, sx, sy, sz, sw, sV, sIdx); break;
            default: fps_loop<8>(b, off, nEff, cnt, comp, sx, sy, sz, sw, sV, sIdx); break;
        }
    } else {
        // ---- gmem fallback (rare; correctness net) ----
        float* __restrict__ D = g_dmin[bs];
        float4 p0 = comp[0];
        if (tid == 0) g_buf[b][off] = __float_as_int(p0.w);
        float lx = p0.x, ly = p0.y, lz = p0.z;
        for (int j = 1; j < nEff; j++) {
            float vmax = -CUDART_INF_F;
            unsigned vidx = 0x7fffffffu;
            for (int i = tid; i < cnt; i += FT) {
                float4 p = comp[i];
                float ax = __fsub_rn(p.x, lx), ay = __fsub_rn(p.y, ly), az = __fsub_rn(p.z, lz);
                float d2 = __fadd_rn(__fadd_rn(__fmul_rn(ax, ax), __fmul_rn(ay, ay)),
                                     __fmul_rn(az, az));
                float dmn = (j == 1) ? d2 : fminf(D[i], d2);
                D[i] = dmn;
                if (dmn > vmax) { vmax = dmn; vidx = (unsigned)i; }
            }
            unsigned vb = (vmax < 0.0f) ? 0u : __float_as_uint(vmax);
            unsigned wm = __reduce_max_sync(0xffffffffu, vb);
            unsigned ci = (vb == wm) ? vidx : 0xffffffffu;
            unsigned wi = __reduce_min_sync(0xffffffffu, ci);
            int par = j & 1;
            if (lane == 0) { fV[par][wid] = wm; fI[par][wid] = wi; }
            __syncthreads();
            unsigned bv = fV[par][0], bp = fI[par][0];
            #pragma unroll
            for (int w2 = 1; w2 < NW; w2++) {
                unsigned v = fV[par][w2], i2 = fI[par][w2];
                if (v > bv || (v == bv && i2 < bp)) { bv = v; bp = i2; }
            }
            float4 pw = comp[bp];
            lx = pw.x; ly = pw.y; lz = pw.z;
            if (tid == 0) g_buf[b][off + j] = __float_as_int(pw.w);
        }
    }
}

// ---- gather output ----
__global__ void k_out(const float* __restrict__ points, float* __restrict__ out) {
    int t = blockIdx.x * blockDim.x + threadIdx.x;
    if (t >= BN * KK) return;
    int b = t / KK, i = t - b * KK;
    int cs[NS];
    int total = g_cnt[b][6];
    #pragma unroll
    for (int s = 0; s < NS; s++) { cs[s] = g_cnt[b][s]; total += cs[s]; }
    if (total < 1) total = 1;
    int st = 0;
    #pragma unroll
    for (int s = 0; s < NS; s++) {
        float q = __fdiv_rn(__fmul_rn((float)cs[s], 2048.0f), (float)total);
        int n = (int)ceilf(q);
        if (n > cs[s]) n = cs[s];
        st += n;
    }
    if (st < 1) st = 1;
    int src = g_buf[b][i % st];
    const float* p = points + ((size_t)b * NP + src) * 3;
    out[3 * t + 0] = p[0];
    out[3 * t + 1] = p[1];
    out[3 * t + 2] = p[2];
}

extern "C" void kernel_launch(void* const* d_in, const int* in_sizes, int n_in,
                              void* d_out, int out_size) {
    const float* points = (const float*)d_in[0];  // [2,65536,3] f32
    const float* rois   = (const float*)d_in[1];  // [2,128,7]  f32
    float* out = (float*)d_out;                   // [2,2048,3] f32

    cudaFuncSetAttribute(k_fps6, cudaFuncAttributeMaxDynamicSharedMemorySize, SMEM_FPS);

    dim3 gc(NP / 256, BN);
    k_classify<<<gc, 256>>>(points, rois);
    k_compact<<<NBS + BN, 1024>>>(points);
    k_fps6<<<NBS, FT, SMEM_FPS>>>();
    k_out<<<(BN * KK + 255) / 256, 256>>>(points, out);
}